// round 15
// baseline (speedup 1.0000x reference)
#include <cuda_runtime.h>
#include <cstdint>

#define BB 2
#define SS 1024
#define DD 128
#define QT 64
#define NT 16   // SS/QT

// ---------------- scratch (static device globals; no allocation) ----------------
__device__ float g_Q[BB*SS*DD];
__device__ float g_K[BB*SS*DD];
__device__ float g_V[BB*SS*DD];
__device__ float g_rowK[BB*SS];
__device__ float g_segsum[BB*NT*DD];
__device__ float g_suffV[BB*SS*DD];
__device__ float g_partOut[(size_t)BB*NT*NT*QT*DD];   // 16 MB
__device__ float g_partZ[BB*NT*NT*QT];

__device__ __forceinline__ float sigmoidf_fast(float v) {
    return 1.0f / (1.0f + __expf(-v));
}

// ---------------- kernel 1: QKV = act(x @ W + b), double-buffered staging ----------
// grid (32 row-tiles, 3 matrices), 256 threads. 64 rows x 128 cols per block.
// Chunk i+1's gmem loads are issued into registers before computing chunk i,
// stored to the alternate smem buffer after — one sync per K-chunk.
// Dynamic smem: 2 x (xs[64][33] + ws[32][128]) = 49664 B.
#define XS_SZ (64 * 33)
#define WS_SZ (32 * 128)
#define BUF_SZ (XS_SZ + WS_SZ)
#define SMEM_QKV (2 * BUF_SZ * 4)

__global__ void qkv_kernel(const float* __restrict__ x,
                           const float* __restrict__ wq, const float* __restrict__ bq,
                           const float* __restrict__ wk, const float* __restrict__ bk,
                           const float* __restrict__ wv, const float* __restrict__ bv) {
    extern __shared__ float qsm[];
    const int mat = blockIdx.y;
    const float* w    = (mat == 0) ? wq : (mat == 1) ? wk : wv;
    const float* bias = (mat == 0) ? bq : (mat == 1) ? bk : bv;
    float* out        = (mat == 0) ? g_Q : (mat == 1) ? g_K : g_V;
    const bool sig = (mat < 2);

    const int r0 = blockIdx.x * 64;
    const int tid = threadIdx.x;
    const int ty = tid >> 4, tx = tid & 15;

    // per-thread staging coordinates (fixed across chunks)
    const int xr_r[8] = { (tid) >> 5, (tid + 256) >> 5, (tid + 512) >> 5, (tid + 768) >> 5,
                          (tid + 1024) >> 5, (tid + 1280) >> 5, (tid + 1536) >> 5, (tid + 1792) >> 5 };
    const int xr_c = tid & 31;   // col within 32-chunk (same for all l since 256 ≡ 0 mod 32)

    float acc[4][8];
#pragma unroll
    for (int a = 0; a < 4; a++)
#pragma unroll
        for (int c = 0; c < 8; c++) acc[a][c] = 0.0f;

    {   // preload chunk 0 into buffer 0
        float* xs0 = qsm;
        float* ws0 = qsm + XS_SZ;
#pragma unroll
        for (int l = 0; l < 8; l++)
            xs0[xr_r[l] * 33 + xr_c] = x[(size_t)(r0 + xr_r[l]) * DD + xr_c];
#pragma unroll
        for (int l = 0; l < 16; l++) {
            int idx = tid + l * 256;
            int i = idx >> 7, j = idx & 127;
            ws0[i * 128 + j] = w[(size_t)i * DD + j];
        }
    }
    __syncthreads();

    for (int it = 0; it < 4; it++) {
        const float* xs = qsm + (it & 1) * BUF_SZ;
        const float* ws = xs + XS_SZ;

        // issue next chunk's gmem loads early (latency overlapped by compute)
        float xr[8], wr[16];
        if (it < 3) {
#pragma unroll
            for (int l = 0; l < 8; l++)
                xr[l] = x[(size_t)(r0 + xr_r[l]) * DD + (it + 1) * 32 + xr_c];
#pragma unroll
            for (int l = 0; l < 16; l++) {
                int idx = tid + l * 256;
                int i = idx >> 7, j = idx & 127;
                wr[l] = w[(size_t)((it + 1) * 32 + i) * DD + j];
            }
        }

#pragma unroll
        for (int i = 0; i < 32; i++) {
            float xv[4];
#pragma unroll
            for (int a = 0; a < 4; a++) xv[a] = xs[(ty * 4 + a) * 33 + i];
            const float4 w0 = *(const float4*)&ws[i * 128 + tx * 8];
            const float4 w1 = *(const float4*)&ws[i * 128 + tx * 8 + 4];
#pragma unroll
            for (int a = 0; a < 4; a++) {
                acc[a][0] += xv[a] * w0.x;  acc[a][1] += xv[a] * w0.y;
                acc[a][2] += xv[a] * w0.z;  acc[a][3] += xv[a] * w0.w;
                acc[a][4] += xv[a] * w1.x;  acc[a][5] += xv[a] * w1.y;
                acc[a][6] += xv[a] * w1.z;  acc[a][7] += xv[a] * w1.w;
            }
        }

        if (it < 3) {   // store prefetched chunk to the other buffer
            float* xsn = qsm + ((it + 1) & 1) * BUF_SZ;
            float* wsn = xsn + XS_SZ;
#pragma unroll
            for (int l = 0; l < 8; l++)
                xsn[xr_r[l] * 33 + xr_c] = xr[l];
#pragma unroll
            for (int l = 0; l < 16; l++) {
                int idx = tid + l * 256;
                int i = idx >> 7, j = idx & 127;
                wsn[i * 128 + j] = wr[l];
            }
        }
        __syncthreads();
    }

    float bv8[8];
#pragma unroll
    for (int c = 0; c < 8; c++) bv8[c] = bias[tx * 8 + c];

    float colpart[8];
#pragma unroll
    for (int c = 0; c < 8; c++) colpart[c] = 0.0f;

#pragma unroll
    for (int a = 0; a < 4; a++) {
        float v[8];
#pragma unroll
        for (int c = 0; c < 8; c++) {
            float t = acc[a][c] + bv8[c];
            v[c] = sig ? sigmoidf_fast(t) : t;
        }
        float* op = out + (size_t)(r0 + ty * 4 + a) * DD + tx * 8;
        *(float4*)op       = make_float4(v[0], v[1], v[2], v[3]);
        *(float4*)(op + 4) = make_float4(v[4], v[5], v[6], v[7]);

        if (mat == 1) {
            float rs = ((v[0] + v[1]) + (v[2] + v[3])) + ((v[4] + v[5]) + (v[6] + v[7]));
            rs += __shfl_xor_sync(0xffffffffu, rs, 1);
            rs += __shfl_xor_sync(0xffffffffu, rs, 2);
            rs += __shfl_xor_sync(0xffffffffu, rs, 4);
            rs += __shfl_xor_sync(0xffffffffu, rs, 8);
            if (tx == 0) g_rowK[r0 + ty * 4 + a] = rs;
        } else if (mat == 2) {
#pragma unroll
            for (int c = 0; c < 8; c++) colpart[c] += v[c];
        }
    }

    if (mat == 2) {
        // column sums over this block's 64 rows -> g_segsum[blockIdx.x][:]
        float* red = qsm;   // reuse buffer 0 (all compute done; loop-end sync passed)
        __syncthreads();
#pragma unroll
        for (int c = 0; c < 8; c++) red[ty * 128 + tx * 8 + c] = colpart[c];
        __syncthreads();
        if (tid < 128) {
            float s = 0.0f;
#pragma unroll
            for (int t = 0; t < 16; t++) s += red[t * 128 + tid];
            g_segsum[blockIdx.x * DD + tid] = s;
        }
    }
}

// ---------------- kernel 2: suffix sums of V (MLP-friendly) ----------------
__global__ void suffix_kernel() {
    const int b = blockIdx.x >> 4, seg = blockIdx.x & 15, d = threadIdx.x;

    float acc = 0.0f;
#pragma unroll
    for (int sg = 0; sg < NT; sg++) {
        float v = (sg > seg) ? g_segsum[(b * NT + sg) * DD + d] : 0.0f;
        acc += v;
    }

    const float* vbase = g_V    + ((size_t)b * SS + seg * 64) * DD + d;
    float*       sbase = g_suffV + ((size_t)b * SS + seg * 64) * DD + d;

#pragma unroll
    for (int i0 = 56; i0 >= 0; i0 -= 8) {
        float v[8];
#pragma unroll
        for (int j = 0; j < 8; j++) v[j] = vbase[(size_t)(i0 + j) * DD];
#pragma unroll
        for (int j = 7; j >= 0; j--) {
            sbase[(size_t)(i0 + j) * DD] = acc;
            acc += v[j];
        }
    }
}

// ---------------- kernel 3: main fused truth + exp + partial (w @ V) ----------------
// grid (kt=16, qt=16, b=2), 256 threads. smem 84KB -> 2 CTAs/SM.
#define QS_STR 129
#define WS_STR 68
#define SMEM_MAIN ((64*QS_STR*2 + 64*WS_STR + 64) * 4)

__global__ void __launch_bounds__(256, 2) main_kernel(float* __restrict__ truth) {
    extern __shared__ float sm[];
    float* Qs    = sm;                    // [64][129] -> later V [64][128]
    float* Ks    = Qs + 64 * QS_STR;      // [64][129]
    float* Ws    = Ks + 64 * QS_STR;      // [64][68]
    float* rowKs = Ws + 64 * WS_STR;      // [64]
    float* Vs    = Qs;                    // reuse (stride 128, 16B aligned)

    const int kt = blockIdx.x, qt = blockIdx.y, b = blockIdx.z;
    const int tid = threadIdx.x;
    const int qb = qt * QT, kb = kt * QT;

    if (kt > qt) {   // strictly-upper tile: zero-fill truth and exit
        int r = tid >> 4, c4 = tid & 15;
        float4 z = make_float4(0.f, 0.f, 0.f, 0.f);
#pragma unroll
        for (int rr = 0; rr < 4; rr++) {
            int row = r + rr * 16;
            *(float4*)&truth[((size_t)(b * SS + qb + row)) * SS + kb + c4 * 4] = z;
        }
        return;
    }

    {   // stage Q, K
        const float* Qg = g_Q + ((size_t)b * SS + qb) * DD;
        const float* Kg = g_K + ((size_t)b * SS + kb) * DD;
#pragma unroll
        for (int l = 0; l < 32; l++) {
            int idx = tid + l * 256;
            int r = idx >> 7, dd = idx & 127;
            Qs[r * QS_STR + dd] = Qg[idx];
            Ks[r * QS_STR + dd] = Kg[idx];
        }
        if (tid < 64) rowKs[tid] = g_rowK[b * SS + kb + tid];
    }
    __syncthreads();

    const int ty = tid >> 4, tx = tid & 15;
    const float* qp = Qs + (ty * 4) * QS_STR;
    const float* kp = Ks + (tx * 4) * QS_STR;

    float acc[4][4];
#pragma unroll
    for (int a = 0; a < 4; a++)
#pragma unroll
        for (int j = 0; j < 4; j++) acc[a][j] = 0.0f;

#pragma unroll 8
    for (int dd = 0; dd < DD; dd++) {
        float qv[4], kv[4], cv[4];
#pragma unroll
        for (int a = 0; a < 4; a++) qv[a] = qp[a * QS_STR + dd];
#pragma unroll
        for (int j = 0; j < 4; j++) { kv[j] = kp[j * QS_STR + dd]; cv[j] = 1.0f - kv[j]; }
#pragma unroll
        for (int a = 0; a < 4; a++)
#pragma unroll
            for (int j = 0; j < 4; j++)
                if (qv[a] <= kv[j]) acc[a][j] += cv[j];
    }

    // truth values + softmax weights
    float wv_[4][4];
#pragma unroll
    for (int a = 0; a < 4; a++) {
        int qg = qb + ty * 4 + a;
#pragma unroll
        for (int j = 0; j < 4; j++) {
            int kg = kb + tx * 4 + j;
            float t = (rowKs[tx * 4 + j] + acc[a][j]) * (1.0f / DD);
            bool valid = (kg <= qg);
            t = valid ? t : 0.0f;
            Ws[(ty * 4 + a) * WS_STR + tx * 4 + j] = t;
            wv_[a][j] = valid ? __expf(10.0f * t) : 0.0f;
        }
    }
    __syncthreads();

    {   // coalesced truth store
        int r = tid >> 4, c4 = tid & 15;
#pragma unroll
        for (int rr = 0; rr < 4; rr++) {
            int row = r + rr * 16;
            float4 tv = *(float4*)&Ws[row * WS_STR + c4 * 4];
            *(float4*)&truth[((size_t)(b * SS + qb + row)) * SS + kb + c4 * 4] = tv;
        }
    }
    __syncthreads();   // Qs (and truth values in Ws) fully consumed

    {   // stage V into the Q buffer (stride 128)
        const float* Vg = g_V + ((size_t)b * SS + kb) * DD;
#pragma unroll
        for (int l = 0; l < 32; l++) {
            int idx = tid + l * 256;
            Vs[idx] = Vg[idx];
        }
    }

    // overwrite Ws with weights
#pragma unroll
    for (int a = 0; a < 4; a++)
#pragma unroll
        for (int j = 0; j < 4; j++)
            Ws[(ty * 4 + a) * WS_STR + tx * 4 + j] = wv_[a][j];

    // partial Z per q-row: reduce across the 16 tx lanes (lane bits 0-3)
    const int slot = (b * NT + qt) * NT + kt;
    {
        float rs[4];
#pragma unroll
        for (int a = 0; a < 4; a++)
            rs[a] = wv_[a][0] + wv_[a][1] + wv_[a][2] + wv_[a][3];
#pragma unroll
        for (int a = 0; a < 4; a++) {
            rs[a] += __shfl_xor_sync(0xffffffffu, rs[a], 8);
            rs[a] += __shfl_xor_sync(0xffffffffu, rs[a], 4);
            rs[a] += __shfl_xor_sync(0xffffffffu, rs[a], 2);
            rs[a] += __shfl_xor_sync(0xffffffffu, rs[a], 1);
        }
        if (tx == 0) {
#pragma unroll
            for (int a = 0; a < 4; a++)
                g_partZ[(size_t)slot * QT + ty * 4 + a] = rs[a];
        }
    }
    __syncthreads();

    // partial out = W(64x64) @ V(64x128); thread tile 4q x 8d
    float oacc[4][8];
#pragma unroll
    for (int a = 0; a < 4; a++)
#pragma unroll
        for (int c = 0; c < 8; c++) oacc[a][c] = 0.0f;

#pragma unroll 4
    for (int kk = 0; kk < QT; kk++) {
        float wr[4];
#pragma unroll
        for (int a = 0; a < 4; a++) wr[a] = Ws[(ty * 4 + a) * WS_STR + kk];
        const float4 va = *(const float4*)&Vs[kk * DD + tx * 8];
        const float4 vb = *(const float4*)&Vs[kk * DD + tx * 8 + 4];
#pragma unroll
        for (int a = 0; a < 4; a++) {
            oacc[a][0] += wr[a] * va.x;  oacc[a][1] += wr[a] * va.y;
            oacc[a][2] += wr[a] * va.z;  oacc[a][3] += wr[a] * va.w;
            oacc[a][4] += wr[a] * vb.x;  oacc[a][5] += wr[a] * vb.y;
            oacc[a][6] += wr[a] * vb.z;  oacc[a][7] += wr[a] * vb.w;
        }
    }
    float* po = g_partOut + (size_t)slot * QT * DD;
#pragma unroll
    for (int a = 0; a < 4; a++) {
        *(float4*)&po[(ty * 4 + a) * DD + tx * 8] =
            make_float4(oacc[a][0], oacc[a][1], oacc[a][2], oacc[a][3]);
        *(float4*)&po[(ty * 4 + a) * DD + tx * 8 + 4] =
            make_float4(oacc[a][4], oacc[a][5], oacc[a][6], oacc[a][7]);
    }
}

// ---------------- kernel 4: combine partials — one thread per output FLOAT4 --------
// grid (qt=16, b=2, rg=16), 128 threads: 4 rows x 32 float4-cols per block.
__global__ void combine_kernel(float* __restrict__ out) {
    const int qt = blockIdx.x, b = blockIdx.y, rg = blockIdx.z;
    const int tid = threadIdx.x;
    const int rl  = tid >> 5;            // 0..3
    const int f4c = tid & 31;            // 0..31
    const int row = rg * 4 + rl;         // 0..63
    const int e4  = row * 32 + f4c;      // float4 index within a 64x128 tile (2048)
    const int base = (b * NT + qt) * NT;
    const float4* pb = (const float4*)g_partOut;

    float sx = 0.f, sy = 0.f, sz = 0.f, sw = 0.f, z = 0.f;
    int kt = 0;
    for (; kt + 3 <= qt; kt += 4) {
        const float4 v0 = pb[(size_t)(base + kt    ) * 2048 + e4];
        const float4 v1 = pb[(size_t)(base + kt + 1) * 2048 + e4];
        const float4 v2 = pb[(size_t)(base + kt + 2) * 2048 + e4];
        const float4 v3 = pb[(size_t)(base + kt + 3) * 2048 + e4];
        float z0 = g_partZ[(size_t)(base + kt    ) * QT + row];
        float z1 = g_partZ[(size_t)(base + kt + 1) * QT + row];
        float z2 = g_partZ[(size_t)(base + kt + 2) * QT + row];
        float z3 = g_partZ[(size_t)(base + kt + 3) * QT + row];
        sx += (v0.x + v1.x) + (v2.x + v3.x);
        sy += (v0.y + v1.y) + (v2.y + v3.y);
        sz += (v0.z + v1.z) + (v2.z + v3.z);
        sw += (v0.w + v1.w) + (v2.w + v3.w);
        z  += (z0 + z1) + (z2 + z3);
    }
    for (; kt <= qt; kt++) {
        const float4 v = pb[(size_t)(base + kt) * 2048 + e4];
        sx += v.x; sy += v.y; sz += v.z; sw += v.w;
        z += g_partZ[(size_t)(base + kt) * QT + row];
    }

    const int qg = qt * QT + row;
    const float Z = z + (float)(SS - 1 - qg);
    const float r = 1.0f / Z;
    const size_t g4 = ((size_t)b * SS + qg) * 32 + f4c;   // float4 index into [*,128]
    const float4 s = ((const float4*)g_suffV)[g4];
    float4 o;
    o.x = (sx + s.x) * r;  o.y = (sy + s.y) * r;
    o.z = (sz + s.z) * r;  o.w = (sw + s.w) * r;
    ((float4*)out)[g4] = o;
}

// ---------------- launch ----------------
extern "C" void kernel_launch(void* const* d_in, const int* in_sizes, int n_in,
                              void* d_out, int out_size) {
    const float* x  = (const float*)d_in[0];
    const float* wq = (const float*)d_in[1];
    const float* bq = (const float*)d_in[2];
    const float* wk = (const float*)d_in[3];
    const float* bk = (const float*)d_in[4];
    const float* wv = (const float*)d_in[5];
    const float* bv = (const float*)d_in[6];
    float* out = (float*)d_out;
    float* truth = out + (size_t)BB * SS * DD;   // output first, then attention_truth

    cudaFuncSetAttribute(qkv_kernel, cudaFuncAttributeMaxDynamicSharedMemorySize, SMEM_QKV);
    cudaFuncSetAttribute(main_kernel, cudaFuncAttributeMaxDynamicSharedMemorySize, SMEM_MAIN);

    qkv_kernel<<<dim3(32, 3), 256, SMEM_QKV>>>(x, wq, bq, wk, bk, wv, bv);
    suffix_kernel<<<BB * NT, 128>>>();
    main_kernel<<<dim3(NT, NT, BB), 256, SMEM_MAIN>>>(truth);
    combine_kernel<<<dim3(NT, BB, 16), 128>>>(out);
}

// round 16
// speedup vs baseline: 1.0433x; 1.0433x over previous
#include <cuda_runtime.h>
#include <cstdint>

#define BB 2
#define SS 1024
#define DD 128
#define QT 64
#define NT 16   // SS/QT

// ---------------- scratch (static device globals; no allocation) ----------------
__device__ float g_Q[BB*SS*DD];
__device__ float g_K[BB*SS*DD];
__device__ float g_V[BB*SS*DD];
__device__ float g_rowK[BB*SS];
__device__ float g_segsum[BB*NT*DD];
__device__ float g_suffV[BB*SS*DD];
__device__ float g_partOut[(size_t)BB*NT*NT*QT*DD];   // 16 MB
__device__ float g_partZ[BB*NT*NT*QT];

__device__ __forceinline__ float sigmoidf_fast(float v) {
    return 1.0f / (1.0f + __expf(-v));
}

// ---------------- kernel 1: QKV = act(x @ W + b), fused rowK / segsum epilogues ----
// grid (32 row-tiles, 3 matrices), 256 threads. 64 rows x 128 cols per block.
__global__ void qkv_kernel(const float* __restrict__ x,
                           const float* __restrict__ wq, const float* __restrict__ bq,
                           const float* __restrict__ wk, const float* __restrict__ bk,
                           const float* __restrict__ wv, const float* __restrict__ bv) {
    __shared__ float xs[64][33];
    __shared__ float ws[32][128];
    const int mat = blockIdx.y;
    const float* w    = (mat == 0) ? wq : (mat == 1) ? wk : wv;
    const float* bias = (mat == 0) ? bq : (mat == 1) ? bk : bv;
    float* out        = (mat == 0) ? g_Q : (mat == 1) ? g_K : g_V;
    const bool sig = (mat < 2);

    const int r0 = blockIdx.x * 64;
    const int tid = threadIdx.x;
    const int ty = tid >> 4, tx = tid & 15;

    float acc[4][8];
#pragma unroll
    for (int a = 0; a < 4; a++)
#pragma unroll
        for (int c = 0; c < 8; c++) acc[a][c] = 0.0f;

    for (int it = 0; it < 4; it++) {
#pragma unroll
        for (int l = 0; l < 8; l++) {
            int idx = tid + l * 256;
            int r = idx >> 5, col = idx & 31;
            xs[r][col] = x[(size_t)(r0 + r) * DD + it * 32 + col];
        }
#pragma unroll
        for (int l = 0; l < 16; l++) {
            int idx = tid + l * 256;
            int i = idx >> 7, j = idx & 127;
            ws[i][j] = w[(size_t)(it * 32 + i) * DD + j];
        }
        __syncthreads();
#pragma unroll
        for (int i = 0; i < 32; i++) {
            float xv[4];
#pragma unroll
            for (int a = 0; a < 4; a++) xv[a] = xs[ty * 4 + a][i];
            const float4 w0 = *(const float4*)&ws[i][tx * 8];
            const float4 w1 = *(const float4*)&ws[i][tx * 8 + 4];
#pragma unroll
            for (int a = 0; a < 4; a++) {
                acc[a][0] += xv[a] * w0.x;  acc[a][1] += xv[a] * w0.y;
                acc[a][2] += xv[a] * w0.z;  acc[a][3] += xv[a] * w0.w;
                acc[a][4] += xv[a] * w1.x;  acc[a][5] += xv[a] * w1.y;
                acc[a][6] += xv[a] * w1.z;  acc[a][7] += xv[a] * w1.w;
            }
        }
        __syncthreads();
    }
    float bv8[8];
#pragma unroll
    for (int c = 0; c < 8; c++) bv8[c] = bias[tx * 8 + c];

    float colpart[8];
#pragma unroll
    for (int c = 0; c < 8; c++) colpart[c] = 0.0f;

#pragma unroll
    for (int a = 0; a < 4; a++) {
        float v[8];
#pragma unroll
        for (int c = 0; c < 8; c++) {
            float t = acc[a][c] + bv8[c];
            v[c] = sig ? sigmoidf_fast(t) : t;
        }
        float* op = out + (size_t)(r0 + ty * 4 + a) * DD + tx * 8;
        *(float4*)op       = make_float4(v[0], v[1], v[2], v[3]);
        *(float4*)(op + 4) = make_float4(v[4], v[5], v[6], v[7]);

        if (mat == 1) {
            float rs = ((v[0] + v[1]) + (v[2] + v[3])) + ((v[4] + v[5]) + (v[6] + v[7]));
            rs += __shfl_xor_sync(0xffffffffu, rs, 1);
            rs += __shfl_xor_sync(0xffffffffu, rs, 2);
            rs += __shfl_xor_sync(0xffffffffu, rs, 4);
            rs += __shfl_xor_sync(0xffffffffu, rs, 8);
            if (tx == 0) g_rowK[r0 + ty * 4 + a] = rs;
        } else if (mat == 2) {
#pragma unroll
            for (int c = 0; c < 8; c++) colpart[c] += v[c];
        }
    }

    if (mat == 2) {
        __syncthreads();
#pragma unroll
        for (int c = 0; c < 8; c++) ws[ty][tx * 8 + c] = colpart[c];
        __syncthreads();
        if (tid < 128) {
            float s = 0.0f;
#pragma unroll
            for (int t = 0; t < 16; t++) s += ws[t][tid];
            g_segsum[blockIdx.x * DD + tid] = s;
        }
    }
}

// ---------------- kernel 2: main fused truth + exp + partial (w @ V); suffix merged -
// grid (x=NT+1, qt=16, b=2), 256 threads. smem 84KB -> 2 CTAs/SM.
// x in [0,NT): k-tile kt=x.  x == NT: suffix-sum role (seg=qt) — suffV is consumed
// only by combine_kernel, so running it alongside main is dependency-safe.
#define QS_STR 129
#define WS_STR 68
#define SMEM_MAIN ((64*QS_STR*2 + 64*WS_STR + 64) * 4)

__global__ void __launch_bounds__(256, 2) main_kernel(float* __restrict__ truth) {
    extern __shared__ float sm[];
    float* Qs    = sm;                    // [64][129] -> later V [64][128]
    float* Ks    = Qs + 64 * QS_STR;      // [64][129]
    float* Ws    = Ks + 64 * QS_STR;      // [64][68]
    float* rowKs = Ws + 64 * WS_STR;      // [64]
    float* Vs    = Qs;                    // reuse (stride 128, 16B aligned)

    const int kt = blockIdx.x, qt = blockIdx.y, b = blockIdx.z;
    const int tid = threadIdx.x;

    if (kt == NT) {   // ---- suffix-sum role (seg = qt) ----
        if (tid >= 128) return;
        const int seg = qt, d = tid;
        float acc = 0.0f;
#pragma unroll
        for (int sg = 0; sg < NT; sg++) {
            float v = (sg > seg) ? g_segsum[(b * NT + sg) * DD + d] : 0.0f;
            acc += v;
        }
        const float* vbase = g_V     + ((size_t)b * SS + seg * 64) * DD + d;
        float*       sbase = g_suffV + ((size_t)b * SS + seg * 64) * DD + d;
#pragma unroll
        for (int i0 = 56; i0 >= 0; i0 -= 8) {
            float v[8];
#pragma unroll
            for (int j = 0; j < 8; j++) v[j] = vbase[(size_t)(i0 + j) * DD];
#pragma unroll
            for (int j = 7; j >= 0; j--) {
                sbase[(size_t)(i0 + j) * DD] = acc;
                acc += v[j];
            }
        }
        return;
    }

    const int qb = qt * QT, kb = kt * QT;

    if (kt > qt) {   // strictly-upper tile: zero-fill truth and exit
        int r = tid >> 4, c4 = tid & 15;
        float4 z = make_float4(0.f, 0.f, 0.f, 0.f);
#pragma unroll
        for (int rr = 0; rr < 4; rr++) {
            int row = r + rr * 16;
            *(float4*)&truth[((size_t)(b * SS + qb + row)) * SS + kb + c4 * 4] = z;
        }
        return;
    }

    {   // stage Q, K
        const float* Qg = g_Q + ((size_t)b * SS + qb) * DD;
        const float* Kg = g_K + ((size_t)b * SS + kb) * DD;
#pragma unroll
        for (int l = 0; l < 32; l++) {
            int idx = tid + l * 256;
            int r = idx >> 7, dd = idx & 127;
            Qs[r * QS_STR + dd] = Qg[idx];
            Ks[r * QS_STR + dd] = Kg[idx];
        }
        if (tid < 64) rowKs[tid] = g_rowK[b * SS + kb + tid];
    }
    __syncthreads();

    const int ty = tid >> 4, tx = tid & 15;
    const float* qp = Qs + (ty * 4) * QS_STR;
    const float* kp = Ks + (tx * 4) * QS_STR;

    float acc[4][4];
#pragma unroll
    for (int a = 0; a < 4; a++)
#pragma unroll
        for (int j = 0; j < 4; j++) acc[a][j] = 0.0f;

#pragma unroll 8
    for (int dd = 0; dd < DD; dd++) {
        float qv[4], kv[4], cv[4];
#pragma unroll
        for (int a = 0; a < 4; a++) qv[a] = qp[a * QS_STR + dd];
#pragma unroll
        for (int j = 0; j < 4; j++) { kv[j] = kp[j * QS_STR + dd]; cv[j] = 1.0f - kv[j]; }
#pragma unroll
        for (int a = 0; a < 4; a++)
#pragma unroll
            for (int j = 0; j < 4; j++)
                if (qv[a] <= kv[j]) acc[a][j] += cv[j];
    }

    // truth values + softmax weights
    float wv_[4][4];
#pragma unroll
    for (int a = 0; a < 4; a++) {
        int qg = qb + ty * 4 + a;
#pragma unroll
        for (int j = 0; j < 4; j++) {
            int kg = kb + tx * 4 + j;
            float t = (rowKs[tx * 4 + j] + acc[a][j]) * (1.0f / DD);
            bool valid = (kg <= qg);
            t = valid ? t : 0.0f;
            Ws[(ty * 4 + a) * WS_STR + tx * 4 + j] = t;
            wv_[a][j] = valid ? __expf(10.0f * t) : 0.0f;
        }
    }
    __syncthreads();

    {   // coalesced truth store
        int r = tid >> 4, c4 = tid & 15;
#pragma unroll
        for (int rr = 0; rr < 4; rr++) {
            int row = r + rr * 16;
            float4 tv = *(float4*)&Ws[row * WS_STR + c4 * 4];
            *(float4*)&truth[((size_t)(b * SS + qb + row)) * SS + kb + c4 * 4] = tv;
        }
    }
    __syncthreads();   // Qs (and truth values in Ws) fully consumed

    {   // stage V into the Q buffer (stride 128)
        const float* Vg = g_V + ((size_t)b * SS + kb) * DD;
#pragma unroll
        for (int l = 0; l < 32; l++) {
            int idx = tid + l * 256;
            Vs[idx] = Vg[idx];
        }
    }

    // overwrite Ws with weights
#pragma unroll
    for (int a = 0; a < 4; a++)
#pragma unroll
        for (int j = 0; j < 4; j++)
            Ws[(ty * 4 + a) * WS_STR + tx * 4 + j] = wv_[a][j];

    // partial Z per q-row: reduce across the 16 tx lanes (lane bits 0-3)
    const int slot = (b * NT + qt) * NT + kt;
    {
        float rs[4];
#pragma unroll
        for (int a = 0; a < 4; a++)
            rs[a] = wv_[a][0] + wv_[a][1] + wv_[a][2] + wv_[a][3];
#pragma unroll
        for (int a = 0; a < 4; a++) {
            rs[a] += __shfl_xor_sync(0xffffffffu, rs[a], 8);
            rs[a] += __shfl_xor_sync(0xffffffffu, rs[a], 4);
            rs[a] += __shfl_xor_sync(0xffffffffu, rs[a], 2);
            rs[a] += __shfl_xor_sync(0xffffffffu, rs[a], 1);
        }
        if (tx == 0) {
#pragma unroll
            for (int a = 0; a < 4; a++)
                g_partZ[(size_t)slot * QT + ty * 4 + a] = rs[a];
        }
    }
    __syncthreads();

    // partial out = W(64x64) @ V(64x128); thread tile 4q x 8d
    float oacc[4][8];
#pragma unroll
    for (int a = 0; a < 4; a++)
#pragma unroll
        for (int c = 0; c < 8; c++) oacc[a][c] = 0.0f;

#pragma unroll 4
    for (int kk = 0; kk < QT; kk++) {
        float wr[4];
#pragma unroll
        for (int a = 0; a < 4; a++) wr[a] = Ws[(ty * 4 + a) * WS_STR + kk];
        const float4 va = *(const float4*)&Vs[kk * DD + tx * 8];
        const float4 vb = *(const float4*)&Vs[kk * DD + tx * 8 + 4];
#pragma unroll
        for (int a = 0; a < 4; a++) {
            oacc[a][0] += wr[a] * va.x;  oacc[a][1] += wr[a] * va.y;
            oacc[a][2] += wr[a] * va.z;  oacc[a][3] += wr[a] * va.w;
            oacc[a][4] += wr[a] * vb.x;  oacc[a][5] += wr[a] * vb.y;
            oacc[a][6] += wr[a] * vb.z;  oacc[a][7] += wr[a] * vb.w;
        }
    }
    float* po = g_partOut + (size_t)slot * QT * DD;
#pragma unroll
    for (int a = 0; a < 4; a++) {
        *(float4*)&po[(ty * 4 + a) * DD + tx * 8] =
            make_float4(oacc[a][0], oacc[a][1], oacc[a][2], oacc[a][3]);
        *(float4*)&po[(ty * 4 + a) * DD + tx * 8 + 4] =
            make_float4(oacc[a][4], oacc[a][5], oacc[a][6], oacc[a][7]);
    }
}

// ---------------- kernel 3: combine partials — one thread per output FLOAT4 --------
// grid (qt=16, b=2, rg=16), 128 threads: 4 rows x 32 float4-cols per block.
// kt batched 8-deep (two independent 4-accumulators) for more loads in flight.
__global__ void combine_kernel(float* __restrict__ out) {
    const int qt = blockIdx.x, b = blockIdx.y, rg = blockIdx.z;
    const int tid = threadIdx.x;
    const int rl  = tid >> 5;            // 0..3
    const int f4c = tid & 31;            // 0..31
    const int row = rg * 4 + rl;         // 0..63
    const int e4  = row * 32 + f4c;      // float4 index within a 64x128 tile (2048)
    const int base = (b * NT + qt) * NT;
    const float4* pb = (const float4*)g_partOut;

    float sx = 0.f, sy = 0.f, sz = 0.f, sw = 0.f, z = 0.f;
    float tx_ = 0.f, ty_ = 0.f, tz_ = 0.f, tw_ = 0.f, z2 = 0.f;
    int kt = 0;
    for (; kt + 7 <= qt; kt += 8) {
        const float4 v0 = pb[(size_t)(base + kt    ) * 2048 + e4];
        const float4 v1 = pb[(size_t)(base + kt + 1) * 2048 + e4];
        const float4 v2 = pb[(size_t)(base + kt + 2) * 2048 + e4];
        const float4 v3 = pb[(size_t)(base + kt + 3) * 2048 + e4];
        const float4 v4 = pb[(size_t)(base + kt + 4) * 2048 + e4];
        const float4 v5 = pb[(size_t)(base + kt + 5) * 2048 + e4];
        const float4 v6 = pb[(size_t)(base + kt + 6) * 2048 + e4];
        const float4 v7 = pb[(size_t)(base + kt + 7) * 2048 + e4];
        float z0 = g_partZ[(size_t)(base + kt    ) * QT + row];
        float z1 = g_partZ[(size_t)(base + kt + 1) * QT + row];
        float z2a = g_partZ[(size_t)(base + kt + 2) * QT + row];
        float z3 = g_partZ[(size_t)(base + kt + 3) * QT + row];
        float z4 = g_partZ[(size_t)(base + kt + 4) * QT + row];
        float z5 = g_partZ[(size_t)(base + kt + 5) * QT + row];
        float z6 = g_partZ[(size_t)(base + kt + 6) * QT + row];
        float z7 = g_partZ[(size_t)(base + kt + 7) * QT + row];
        sx  += (v0.x + v1.x) + (v2.x + v3.x);
        sy  += (v0.y + v1.y) + (v2.y + v3.y);
        sz  += (v0.z + v1.z) + (v2.z + v3.z);
        sw  += (v0.w + v1.w) + (v2.w + v3.w);
        z   += (z0 + z1) + (z2a + z3);
        tx_ += (v4.x + v5.x) + (v6.x + v7.x);
        ty_ += (v4.y + v5.y) + (v6.y + v7.y);
        tz_ += (v4.z + v5.z) + (v6.z + v7.z);
        tw_ += (v4.w + v5.w) + (v6.w + v7.w);
        z2  += (z4 + z5) + (z6 + z7);
    }
    for (; kt + 3 <= qt; kt += 4) {
        const float4 v0 = pb[(size_t)(base + kt    ) * 2048 + e4];
        const float4 v1 = pb[(size_t)(base + kt + 1) * 2048 + e4];
        const float4 v2 = pb[(size_t)(base + kt + 2) * 2048 + e4];
        const float4 v3 = pb[(size_t)(base + kt + 3) * 2048 + e4];
        float z0 = g_partZ[(size_t)(base + kt    ) * QT + row];
        float z1 = g_partZ[(size_t)(base + kt + 1) * QT + row];
        float z2a = g_partZ[(size_t)(base + kt + 2) * QT + row];
        float z3 = g_partZ[(size_t)(base + kt + 3) * QT + row];
        sx += (v0.x + v1.x) + (v2.x + v3.x);
        sy += (v0.y + v1.y) + (v2.y + v3.y);
        sz += (v0.z + v1.z) + (v2.z + v3.z);
        sw += (v0.w + v1.w) + (v2.w + v3.w);
        z  += (z0 + z1) + (z2a + z3);
    }
    for (; kt <= qt; kt++) {
        const float4 v = pb[(size_t)(base + kt) * 2048 + e4];
        sx += v.x; sy += v.y; sz += v.z; sw += v.w;
        z += g_partZ[(size_t)(base + kt) * QT + row];
    }
    sx += tx_; sy += ty_; sz += tz_; sw += tw_; z += z2;

    const int qg = qt * QT + row;
    const float Z = z + (float)(SS - 1 - qg);
    const float r = 1.0f / Z;
    const size_t g4 = ((size_t)b * SS + qg) * 32 + f4c;   // float4 index into [*,128]
    const float4 s = ((const float4*)g_suffV)[g4];
    float4 o;
    o.x = (sx + s.x) * r;  o.y = (sy + s.y) * r;
    o.z = (sz + s.z) * r;  o.w = (sw + s.w) * r;
    ((float4*)out)[g4] = o;
}

// ---------------- launch ----------------
extern "C" void kernel_launch(void* const* d_in, const int* in_sizes, int n_in,
                              void* d_out, int out_size) {
    const float* x  = (const float*)d_in[0];
    const float* wq = (const float*)d_in[1];
    const float* bq = (const float*)d_in[2];
    const float* wk = (const float*)d_in[3];
    const float* bk = (const float*)d_in[4];
    const float* wv = (const float*)d_in[5];
    const float* bv = (const float*)d_in[6];
    float* out = (float*)d_out;
    float* truth = out + (size_t)BB * SS * DD;   // output first, then attention_truth

    cudaFuncSetAttribute(main_kernel, cudaFuncAttributeMaxDynamicSharedMemorySize, SMEM_MAIN);

    qkv_kernel<<<dim3(32, 3), 256>>>(x, wq, bq, wk, bk, wv, bv);
    main_kernel<<<dim3(NT + 1, NT, BB), 256, SMEM_MAIN>>>(truth);
    combine_kernel<<<dim3(NT, BB, 16), 128>>>(out);
}